// round 2
// baseline (speedup 1.0000x reference)
#include <cuda_runtime.h>
#include <math.h>

#define BB 16
#define NN 768
#define EE 1024
#define HH 16
#define DD 64
#define NEGV (-1e16f)

// Scratch (static device globals; no runtime allocation allowed).
__device__ float g_qh[BB * HH * NN * DD];   // (B,H,N,D)
__device__ float g_kh[BB * HH * NN * DD];
__device__ float g_vh[BB * HH * NN * DD];
__device__ float g_attn[BB * NN * EE];      // (B,N,E) pre-final-projection

__device__ __forceinline__ void f4arr(float4 v, float* a) {
    a[0] = v.x; a[1] = v.y; a[2] = v.z; a[3] = v.w;
}

// ---------------------------------------------------------------------------
// Stage A: per-head projections.  Y[b,h,n,e'] = sum_d X[b,n,h*64+d] * W[h,e',d]
// grid (N/64, B*H, 3), block 256. 64x64 output tile, 4x4 per thread.
// ---------------------------------------------------------------------------
__global__ __launch_bounds__(256) void proj_kernel(
    const float* __restrict__ q, const float* __restrict__ k, const float* __restrict__ v,
    const float* __restrict__ Wq, const float* __restrict__ Wk, const float* __restrict__ Wv)
{
    __shared__ float Xs[64][68];   // [n][d]
    __shared__ float Wt[64][68];   // [d][e']  (transposed W)

    const int which = blockIdx.z;
    const float* X = (which == 0) ? q : (which == 1) ? k : v;
    const float* W = (which == 0) ? Wq : (which == 1) ? Wk : Wv;
    float* Y = (which == 0) ? g_qh : (which == 1) ? g_kh : g_vh;

    const int bh = blockIdx.y;
    const int b = bh >> 4, h = bh & 15;
    const int n0 = blockIdx.x * 64;
    const int tid = threadIdx.x;

    // Load X tile (rows n, cols d): coalesced, conflict-free stores.
    {
        const int rr0 = tid >> 4;
        const int c4 = (tid & 15) * 4;
        const float* src = X + ((size_t)b * NN) * EE + h * DD;
        #pragma unroll
        for (int rr = 0; rr < 64; rr += 16) {
            float4 val = *(const float4*)(src + (size_t)(n0 + rr0 + rr) * EE + c4);
            *(float4*)&Xs[rr0 + rr][c4] = val;
        }
    }
    // Load W transposed: lane map (e = tid&15, dq = (tid>>4)*4) -> conflict-free smem stores.
    {
        const int e0t = tid & 15;
        const int dq = (tid >> 4) * 4;
        const float* wsrc = W + h * DD * DD;
        #pragma unroll
        for (int ee = 0; ee < 64; ee += 16) {
            const int e = e0t + ee;
            float4 wv = *(const float4*)(wsrc + e * DD + dq);
            Wt[dq + 0][e] = wv.x; Wt[dq + 1][e] = wv.y;
            Wt[dq + 2][e] = wv.z; Wt[dq + 3][e] = wv.w;
        }
    }
    __syncthreads();

    const int ty = tid >> 4, tx = tid & 15;
    const int r = ty * 4, c = tx * 4;
    float acc[4][4] = {};

    #pragma unroll
    for (int d4 = 0; d4 < 64; d4 += 4) {
        float xa[4][4], wa[4][4];
        #pragma unroll
        for (int i = 0; i < 4; i++) f4arr(*(const float4*)&Xs[r + i][d4], xa[i]);
        #pragma unroll
        for (int t = 0; t < 4; t++) f4arr(*(const float4*)&Wt[d4 + t][c], wa[t]);
        #pragma unroll
        for (int i = 0; i < 4; i++)
            #pragma unroll
            for (int t = 0; t < 4; t++)
                #pragma unroll
                for (int j = 0; j < 4; j++)
                    acc[i][j] += xa[i][t] * wa[t][j];
    }

    float* dst = Y + (((size_t)bh) * NN + n0 + r) * DD + c;
    #pragma unroll
    for (int i = 0; i < 4; i++) {
        *(float4*)(dst + (size_t)i * DD) =
            make_float4(acc[i][0], acc[i][1], acc[i][2], acc[i][3]);
    }
}

// ---------------------------------------------------------------------------
// Stage B: flash attention per (b,h), 64 query rows per block, online softmax.
// grid (N/64, B*H), block 256, dynamic smem.
// ---------------------------------------------------------------------------
__global__ __launch_bounds__(256) void attn_kernel(const float* __restrict__ mask)
{
    extern __shared__ float sm[];
    float (*Qs)[68]  = (float (*)[68])(sm);               // [q][d], pre-scaled by 1/32
    float (*Kst)[68] = (float (*)[68])(sm + 64 * 68);     // [d][k]  (transposed)
    float (*Vs)[68]  = (float (*)[68])(sm + 2 * 64 * 68); // [k][d]
    float (*Ps)[68]  = (float (*)[68])(sm + 3 * 64 * 68); // [q][k]
    float* sb_bad    = sm + 4 * 64 * 68;                  // [k] 1.0 if masked

    const int bh = blockIdx.y;
    const int b = bh >> 4, h = bh & 15;
    const int q0 = blockIdx.x * 64;
    const int tid = threadIdx.x;
    const int ty = tid >> 4, tx = tid & 15;
    const int r = ty * 4, c = tx * 4;
    const float scale = 0.03125f;  // 1/sqrt(1024)

    const float* qbase = g_qh + ((size_t)bh * NN) * DD;
    const float* kbase = g_kh + ((size_t)bh * NN) * DD;
    const float* vbase = g_vh + ((size_t)bh * NN) * DD;

    // Load Q tile scaled.
    {
        const int rr0 = tid >> 4;
        const int c4 = (tid & 15) * 4;
        #pragma unroll
        for (int rr = 0; rr < 64; rr += 16) {
            float4 val = *(const float4*)(qbase + (size_t)(q0 + rr0 + rr) * DD + c4);
            val.x *= scale; val.y *= scale; val.z *= scale; val.w *= scale;
            *(float4*)&Qs[rr0 + rr][c4] = val;
        }
    }

    bool badq[4];
    #pragma unroll
    for (int i = 0; i < 4; i++) {
        float mv = mask[h * NN + q0 + r + i];
        badq[i] = (mv == -INFINITY);
    }

    float m_i[4], l_i[4], o[4][4];
    #pragma unroll
    for (int i = 0; i < 4; i++) {
        m_i[i] = -INFINITY; l_i[i] = 0.f;
        #pragma unroll
        for (int j = 0; j < 4; j++) o[i][j] = 0.f;
    }

    for (int kt = 0; kt < NN; kt += 64) {
        __syncthreads();  // prior PV reads of Vs/Ps done

        // Load K transposed: lane map (kr = tid&15, dq=(tid>>4)*4) => conflict-free stores.
        {
            const int kr0 = tid & 15;
            const int dq = (tid >> 4) * 4;
            #pragma unroll
            for (int rr = 0; rr < 64; rr += 16) {
                const int kr = kr0 + rr;
                float4 kv = *(const float4*)(kbase + (size_t)(kt + kr) * DD + dq);
                Kst[dq + 0][kr] = kv.x; Kst[dq + 1][kr] = kv.y;
                Kst[dq + 2][kr] = kv.z; Kst[dq + 3][kr] = kv.w;
            }
        }
        // Load V (row-major) + mask flags.
        {
            const int rr0 = tid >> 4;
            const int c4 = (tid & 15) * 4;
            #pragma unroll
            for (int rr = 0; rr < 64; rr += 16) {
                float4 vv = *(const float4*)(vbase + (size_t)(kt + rr0 + rr) * DD + c4);
                *(float4*)&Vs[rr0 + rr][c4] = vv;
            }
            if (tid < 64) {
                float mv = mask[h * NN + kt + tid];
                sb_bad[tid] = (mv == -INFINITY) ? 1.0f : 0.0f;
            }
        }
        __syncthreads();

        // S = (Q/32) K^T
        float s[4][4] = {};
        #pragma unroll
        for (int d4 = 0; d4 < 64; d4 += 4) {
            float qa[4][4], ka[4][4];
            #pragma unroll
            for (int i = 0; i < 4; i++) f4arr(*(const float4*)&Qs[r + i][d4], qa[i]);
            #pragma unroll
            for (int t = 0; t < 4; t++) f4arr(*(const float4*)&Kst[d4 + t][c], ka[t]);
            #pragma unroll
            for (int i = 0; i < 4; i++)
                #pragma unroll
                for (int t = 0; t < 4; t++)
                    #pragma unroll
                    for (int j = 0; j < 4; j++)
                        s[i][j] += qa[i][t] * ka[t][j];
        }

        // Additive mask: exactly one NEG where bad_q | bad_k (matches reference).
        float bk[4] = {sb_bad[c], sb_bad[c + 1], sb_bad[c + 2], sb_bad[c + 3]};
        #pragma unroll
        for (int i = 0; i < 4; i++)
            #pragma unroll
            for (int j = 0; j < 4; j++)
                if (badq[i] || bk[j] != 0.0f) s[i][j] += NEGV;

        // Online softmax (row groups = 16 tx lanes, low 4 bits of lane id).
        #pragma unroll
        for (int i = 0; i < 4; i++) {
            float mx = fmaxf(fmaxf(s[i][0], s[i][1]), fmaxf(s[i][2], s[i][3]));
            #pragma unroll
            for (int w = 1; w < 16; w <<= 1)
                mx = fmaxf(mx, __shfl_xor_sync(0xffffffffu, mx, w));
            const float mnew = fmaxf(m_i[i], mx);
            const float corr = expf(m_i[i] - mnew);   // expf(-inf)=0 on first tile
            float rs = 0.f;
            #pragma unroll
            for (int j = 0; j < 4; j++) {
                float p = expf(s[i][j] - mnew);
                s[i][j] = p; rs += p;
            }
            #pragma unroll
            for (int w = 1; w < 16; w <<= 1)
                rs += __shfl_xor_sync(0xffffffffu, rs, w);
            l_i[i] = l_i[i] * corr + rs;
            m_i[i] = mnew;
            #pragma unroll
            for (int j = 0; j < 4; j++) o[i][j] *= corr;
        }

        #pragma unroll
        for (int i = 0; i < 4; i++)
            *(float4*)&Ps[r + i][c] = make_float4(s[i][0], s[i][1], s[i][2], s[i][3]);
        __syncthreads();

        // O += P @ V
        #pragma unroll
        for (int k4 = 0; k4 < 64; k4 += 4) {
            float pa[4][4], va[4][4];
            #pragma unroll
            for (int i = 0; i < 4; i++) f4arr(*(const float4*)&Ps[r + i][k4], pa[i]);
            #pragma unroll
            for (int t = 0; t < 4; t++) f4arr(*(const float4*)&Vs[k4 + t][c], va[t]);
            #pragma unroll
            for (int i = 0; i < 4; i++)
                #pragma unroll
                for (int t = 0; t < 4; t++)
                    #pragma unroll
                    for (int j = 0; j < 4; j++)
                        o[i][j] += pa[i][t] * va[t][j];
        }
    }

    // Finalize into (B,N,E) layout for the output GEMM.
    float* dst = g_attn + ((size_t)b * NN + q0 + r) * EE + h * DD + c;
    #pragma unroll
    for (int i = 0; i < 4; i++) {
        const float inv = 1.0f / l_i[i];
        *(float4*)(dst + (size_t)i * EE) =
            make_float4(o[i][0] * inv, o[i][1] * inv, o[i][2] * inv, o[i][3] * inv);
    }
}

// ---------------------------------------------------------------------------
// Stage C: out[m][e] = sum_c attn[m][c] * Wf[e][c].  128x128 tile, 8x8/thread.
// grid (E/128, (B*N)/128), block 256.
// ---------------------------------------------------------------------------
__global__ __launch_bounds__(256) void out_gemm_kernel(
    const float* __restrict__ Wf, float* __restrict__ out)
{
    __shared__ float As[8][132];  // [c][m]
    __shared__ float Bs[8][132];  // [c][e]

    const int e0 = blockIdx.x * 128;
    const int m0 = blockIdx.y * 128;
    const int tid = threadIdx.x;
    const int ty = tid >> 4, tx = tid & 15;

    float acc[8][8] = {};

    const int lr = tid >> 1;            // 0..127
    const int lc = (tid & 1) * 4;       // 0 or 4
    const float* Ab = g_attn + (size_t)(m0 + lr) * EE;
    const float* Wb = Wf + (size_t)(e0 + lr) * EE;

    for (int c0 = 0; c0 < EE; c0 += 8) {
        __syncthreads();
        float4 av = *(const float4*)(Ab + c0 + lc);
        float4 wv = *(const float4*)(Wb + c0 + lc);
        As[lc + 0][lr] = av.x; As[lc + 1][lr] = av.y;
        As[lc + 2][lr] = av.z; As[lc + 3][lr] = av.w;
        Bs[lc + 0][lr] = wv.x; Bs[lc + 1][lr] = wv.y;
        Bs[lc + 2][lr] = wv.z; Bs[lc + 3][lr] = wv.w;
        __syncthreads();

        #pragma unroll
        for (int cc = 0; cc < 8; cc++) {
            float a[8], bb[8];
            f4arr(*(const float4*)&As[cc][4 * ty],      a);
            f4arr(*(const float4*)&As[cc][64 + 4 * ty], a + 4);
            f4arr(*(const float4*)&Bs[cc][4 * tx],      bb);
            f4arr(*(const float4*)&Bs[cc][64 + 4 * tx], bb + 4);
            #pragma unroll
            for (int i = 0; i < 8; i++)
                #pragma unroll
                for (int j = 0; j < 8; j++)
                    acc[i][j] += a[i] * bb[j];
        }
    }

    #pragma unroll
    for (int i = 0; i < 8; i++) {
        const int mrow = m0 + ((i < 4) ? (4 * ty + i) : (64 + 4 * ty + (i - 4)));
        float* dst = out + (size_t)mrow * EE + e0;
        *(float4*)(dst + 4 * tx) =
            make_float4(acc[i][0], acc[i][1], acc[i][2], acc[i][3]);
        *(float4*)(dst + 64 + 4 * tx) =
            make_float4(acc[i][4], acc[i][5], acc[i][6], acc[i][7]);
    }
}

// ---------------------------------------------------------------------------
extern "C" void kernel_launch(void* const* d_in, const int* in_sizes, int n_in,
                              void* d_out, int out_size)
{
    const float* q    = (const float*)d_in[0];
    const float* k    = (const float*)d_in[1];
    const float* v    = (const float*)d_in[2];
    const float* mask = (const float*)d_in[3];
    const float* Wq   = (const float*)d_in[4];
    const float* Wk   = (const float*)d_in[5];
    const float* Wv   = (const float*)d_in[6];
    const float* Wf   = (const float*)d_in[7];
    float* out = (float*)d_out;

    const int attn_smem = (4 * 64 * 68 + 64) * (int)sizeof(float);  // 69888 B
    cudaFuncSetAttribute(attn_kernel,
                         cudaFuncAttributeMaxDynamicSharedMemorySize, attn_smem);

    proj_kernel<<<dim3(NN / 64, BB * HH, 3), 256>>>(q, k, v, Wq, Wk, Wv);
    attn_kernel<<<dim3(NN / 64, BB * HH), 256, attn_smem>>>(mask);
    out_gemm_kernel<<<dim3(EE / 128, (BB * NN) / 128), 256>>>(Wf, out);
}

// round 3
// speedup vs baseline: 2.9659x; 2.9659x over previous
#include <cuda_runtime.h>
#include <math.h>
#include <stdint.h>

#define BB 16
#define NN 768
#define EE 1024
#define HH 16
#define DD 64
#define NEGV (-1e16f)

// Scratch (static device globals; no runtime allocation allowed).
// All values stored here are tf32-rounded (valid tf32 bit patterns in fp32).
__device__ float g_qh[BB * HH * NN * DD];   // (B,H,N,D), pre-scaled by 1/32
__device__ float g_kh[BB * HH * NN * DD];
__device__ float g_vh[BB * HH * NN * DD];
__device__ float g_attn[BB * NN * EE];      // (B,N,E) pre-final-projection
__device__ float g_wtf[EE * EE];            // tf32-rounded Wf

// ---------------------------------------------------------------------------
// helpers
// ---------------------------------------------------------------------------
__device__ __forceinline__ uint32_t f2tf(float x) {
    uint32_t r;
    asm("cvt.rna.tf32.f32 %0, %1;" : "=r"(r) : "f"(x));
    return r;
}
__device__ __forceinline__ float f2tf_f(float x) {
    return __uint_as_float(f2tf(x));
}
__device__ __forceinline__ void mma_tf32(float d[4],
                                         uint32_t a0, uint32_t a1, uint32_t a2, uint32_t a3,
                                         uint32_t b0, uint32_t b1) {
    asm volatile(
        "mma.sync.aligned.m16n8k8.row.col.f32.tf32.tf32.f32 "
        "{%0,%1,%2,%3}, {%4,%5,%6,%7}, {%8,%9}, {%0,%1,%2,%3};\n"
        : "+f"(d[0]), "+f"(d[1]), "+f"(d[2]), "+f"(d[3])
        : "r"(a0), "r"(a1), "r"(a2), "r"(a3), "r"(b0), "r"(b1));
}
__device__ __forceinline__ void cp16(void* smem, const void* gmem) {
    uint32_t s = (uint32_t)__cvta_generic_to_shared(smem);
    asm volatile("cp.async.cg.shared.global [%0], [%1], 16;\n" :: "r"(s), "l"(gmem));
}
__device__ __forceinline__ void cp_commit() { asm volatile("cp.async.commit_group;\n"); }
__device__ __forceinline__ void cp_wait1() { asm volatile("cp.async.wait_group 1;\n"); }
__device__ __forceinline__ void cp_wait0() { asm volatile("cp.async.wait_group 0;\n"); }

__device__ __forceinline__ void f4arr(float4 v, float* a) {
    a[0] = v.x; a[1] = v.y; a[2] = v.z; a[3] = v.w;
}

// ---------------------------------------------------------------------------
// Stage A: per-head projections (fp32 math, tf32-rounded output; Q scaled 1/32)
// ---------------------------------------------------------------------------
__global__ __launch_bounds__(256) void proj_kernel(
    const float* __restrict__ q, const float* __restrict__ k, const float* __restrict__ v,
    const float* __restrict__ Wq, const float* __restrict__ Wk, const float* __restrict__ Wv)
{
    __shared__ float Xs[64][68];
    __shared__ float Wt[64][68];

    const int which = blockIdx.z;
    const float* X = (which == 0) ? q : (which == 1) ? k : v;
    const float* W = (which == 0) ? Wq : (which == 1) ? Wk : Wv;
    float* Y = (which == 0) ? g_qh : (which == 1) ? g_kh : g_vh;
    const float oscl = (which == 0) ? 0.03125f : 1.0f;   // fold 1/sqrt(E) into Q

    const int bh = blockIdx.y;
    const int b = bh >> 4, h = bh & 15;
    const int n0 = blockIdx.x * 64;
    const int tid = threadIdx.x;

    {
        const int rr0 = tid >> 4;
        const int c4 = (tid & 15) * 4;
        const float* src = X + ((size_t)b * NN) * EE + h * DD;
        #pragma unroll
        for (int rr = 0; rr < 64; rr += 16) {
            float4 val = *(const float4*)(src + (size_t)(n0 + rr0 + rr) * EE + c4);
            *(float4*)&Xs[rr0 + rr][c4] = val;
        }
    }
    {
        const int e0t = tid & 15;
        const int dq = (tid >> 4) * 4;
        const float* wsrc = W + h * DD * DD;
        #pragma unroll
        for (int ee = 0; ee < 64; ee += 16) {
            const int e = e0t + ee;
            float4 wv = *(const float4*)(wsrc + e * DD + dq);
            Wt[dq + 0][e] = wv.x; Wt[dq + 1][e] = wv.y;
            Wt[dq + 2][e] = wv.z; Wt[dq + 3][e] = wv.w;
        }
    }
    __syncthreads();

    const int ty = tid >> 4, tx = tid & 15;
    const int r = ty * 4, c = tx * 4;
    float acc[4][4] = {};

    #pragma unroll
    for (int d4 = 0; d4 < 64; d4 += 4) {
        float xa[4][4], wa[4][4];
        #pragma unroll
        for (int i = 0; i < 4; i++) f4arr(*(const float4*)&Xs[r + i][d4], xa[i]);
        #pragma unroll
        for (int t = 0; t < 4; t++) f4arr(*(const float4*)&Wt[d4 + t][c], wa[t]);
        #pragma unroll
        for (int i = 0; i < 4; i++)
            #pragma unroll
            for (int t = 0; t < 4; t++)
                #pragma unroll
                for (int j = 0; j < 4; j++)
                    acc[i][j] += xa[i][t] * wa[t][j];
    }

    float* dst = Y + (((size_t)bh) * NN + n0 + r) * DD + c;
    #pragma unroll
    for (int i = 0; i < 4; i++) {
        *(float4*)(dst + (size_t)i * DD) =
            make_float4(f2tf_f(acc[i][0] * oscl), f2tf_f(acc[i][1] * oscl),
                        f2tf_f(acc[i][2] * oscl), f2tf_f(acc[i][3] * oscl));
    }
}

// ---------------------------------------------------------------------------
// Wf -> tf32 prepass
// ---------------------------------------------------------------------------
__global__ __launch_bounds__(256) void cvtW_kernel(const float* __restrict__ Wf)
{
    int i = (blockIdx.x * 256 + threadIdx.x) * 4;
    float4 v = *(const float4*)(Wf + i);
    *(float4*)(g_wtf + i) = make_float4(f2tf_f(v.x), f2tf_f(v.y), f2tf_f(v.z), f2tf_f(v.w));
}

// ---------------------------------------------------------------------------
// Stage B: flash attention with tf32 mma. 128 q-rows/block, 8 warps x m16.
// grid (6, 256), block 256, dynamic smem 79872 B.
// smem layout (floats): Qs[128][76] | Ks[64][76] | Vs[64][72] | madd[768]
// ---------------------------------------------------------------------------
#define QS(r, c_) sm[(r) * 76 + (c_)]
#define KS(r, c_) sm[9728 + (r) * 76 + (c_)]
#define VS(r, c_) sm[14592 + (r) * 72 + (c_)]
#define MADD(i)   sm[19200 + (i)]

__global__ __launch_bounds__(256, 2) void attn_tf32_kernel(const float* __restrict__ mask)
{
    extern __shared__ float sm[];

    const int bh = blockIdx.y;
    const int b = bh >> 4, h = bh & 15;
    const int q0 = blockIdx.x * 128;
    const int tid = threadIdx.x;
    const int w = tid >> 5;
    const int lane = tid & 31;
    const int g = lane >> 2;      // group id: row within m16
    const int qd = lane & 3;      // thread-in-group

    // additive mask row for this head (shared across all ktiles)
    for (int i = tid; i < NN; i += 256)
        MADD(i) = (mask[h * NN + i] == -INFINITY) ? NEGV : 0.f;

    // stage Q tile (already tf32 + scaled)
    const float* qb = g_qh + ((size_t)bh * NN + q0) * DD;
    {
        const int rr = tid >> 4, c4 = (tid & 15) * 4;
        #pragma unroll
        for (int i = 0; i < 8; i++)
            *(float4*)&QS(rr + 16 * i, c4) =
                *(const float4*)(qb + (size_t)(rr + 16 * i) * DD + c4);
    }
    __syncthreads();

    const int qrow = 16 * w + g;
    const float addq0 = MADD(q0 + qrow);
    const float addq1 = MADD(q0 + qrow + 8);

    float m0r = -INFINITY, m1r = -INFINITY, l0 = 0.f, l1 = 0.f;
    float o[8][4] = {};

    const float* kb = g_kh + ((size_t)bh * NN) * DD;
    const float* vb = g_vh + ((size_t)bh * NN) * DD;

    const int shbase = lane & ~3;
    const int s0l = shbase + (qd >> 1);
    const int s2l = shbase + (qd >> 1) + 2;
    const bool odd = qd & 1;

    for (int kt = 0; kt < NN; kt += 64) {
        __syncthreads();
        // load K/V tiles (tf32 data, coalesced)
        {
            const int rr = tid >> 4, c4 = (tid & 15) * 4;
            #pragma unroll
            for (int i = 0; i < 4; i++) {
                *(float4*)&KS(rr + 16 * i, c4) =
                    *(const float4*)(kb + (size_t)(kt + rr + 16 * i) * DD + c4);
                *(float4*)&VS(rr + 16 * i, c4) =
                    *(const float4*)(vb + (size_t)(kt + rr + 16 * i) * DD + c4);
            }
        }
        __syncthreads();

        // S = Q K^T  (A from Qs, B from Ks; conflict-free pads)
        float s[8][4] = {};
        #pragma unroll
        for (int kk = 0; kk < 8; kk++) {
            uint32_t a0 = __float_as_uint(QS(qrow,     kk * 8 + qd));
            uint32_t a1 = __float_as_uint(QS(qrow + 8, kk * 8 + qd));
            uint32_t a2 = __float_as_uint(QS(qrow,     kk * 8 + qd + 4));
            uint32_t a3 = __float_as_uint(QS(qrow + 8, kk * 8 + qd + 4));
            #pragma unroll
            for (int nt = 0; nt < 8; nt++) {
                uint32_t b0 = __float_as_uint(KS(nt * 8 + g, kk * 8 + qd));
                uint32_t b1 = __float_as_uint(KS(nt * 8 + g, kk * 8 + qd + 4));
                mma_tf32(s[nt], a0, a1, a2, a3, b0, b1);
            }
        }

        // mask (exactly one NEGV where badq|badk) + online softmax
        float pm0 = -INFINITY, pm1 = -INFINITY;
        #pragma unroll
        for (int nt = 0; nt < 8; nt++) {
            float2 mk = *(const float2*)&MADD(kt + nt * 8 + 2 * qd);
            s[nt][0] += fmaxf(addq0 + mk.x, NEGV);
            s[nt][1] += fmaxf(addq0 + mk.y, NEGV);
            s[nt][2] += fmaxf(addq1 + mk.x, NEGV);
            s[nt][3] += fmaxf(addq1 + mk.y, NEGV);
            pm0 = fmaxf(pm0, fmaxf(s[nt][0], s[nt][1]));
            pm1 = fmaxf(pm1, fmaxf(s[nt][2], s[nt][3]));
        }
        pm0 = fmaxf(pm0, __shfl_xor_sync(0xffffffffu, pm0, 1));
        pm0 = fmaxf(pm0, __shfl_xor_sync(0xffffffffu, pm0, 2));
        pm1 = fmaxf(pm1, __shfl_xor_sync(0xffffffffu, pm1, 1));
        pm1 = fmaxf(pm1, __shfl_xor_sync(0xffffffffu, pm1, 2));

        const float mn0 = fmaxf(m0r, pm0), mn1 = fmaxf(m1r, pm1);
        const float corr0 = __expf(m0r - mn0), corr1 = __expf(m1r - mn1);
        m0r = mn0; m1r = mn1;

        float rs0 = 0.f, rs1 = 0.f;
        #pragma unroll
        for (int nt = 0; nt < 8; nt++) {
            s[nt][0] = __expf(s[nt][0] - mn0); rs0 += s[nt][0];
            s[nt][1] = __expf(s[nt][1] - mn0); rs0 += s[nt][1];
            s[nt][2] = __expf(s[nt][2] - mn1); rs1 += s[nt][2];
            s[nt][3] = __expf(s[nt][3] - mn1); rs1 += s[nt][3];
        }
        rs0 += __shfl_xor_sync(0xffffffffu, rs0, 1);
        rs0 += __shfl_xor_sync(0xffffffffu, rs0, 2);
        rs1 += __shfl_xor_sync(0xffffffffu, rs1, 1);
        rs1 += __shfl_xor_sync(0xffffffffu, rs1, 2);
        l0 = l0 * corr0 + rs0;
        l1 = l1 * corr1 + rs1;

        #pragma unroll
        for (int dt = 0; dt < 8; dt++) {
            o[dt][0] *= corr0; o[dt][1] *= corr0;
            o[dt][2] *= corr1; o[dt][3] *= corr1;
        }

        // O += P V   (P: C-fragment -> A-fragment via quad shuffles)
        #pragma unroll
        for (int kk = 0; kk < 8; kk++) {
            float e0 = __shfl_sync(0xffffffffu, s[kk][0], s0l);
            float e1 = __shfl_sync(0xffffffffu, s[kk][1], s0l);
            float e2 = __shfl_sync(0xffffffffu, s[kk][2], s0l);
            float e3 = __shfl_sync(0xffffffffu, s[kk][3], s0l);
            float f0 = __shfl_sync(0xffffffffu, s[kk][0], s2l);
            float f1 = __shfl_sync(0xffffffffu, s[kk][1], s2l);
            float f2 = __shfl_sync(0xffffffffu, s[kk][2], s2l);
            float f3 = __shfl_sync(0xffffffffu, s[kk][3], s2l);
            uint32_t a0 = f2tf(odd ? e1 : e0);
            uint32_t a1 = f2tf(odd ? e3 : e2);
            uint32_t a2 = f2tf(odd ? f1 : f0);
            uint32_t a3 = f2tf(odd ? f3 : f2);
            #pragma unroll
            for (int dt = 0; dt < 8; dt++) {
                uint32_t b0 = __float_as_uint(VS(kk * 8 + qd,     dt * 8 + g));
                uint32_t b1 = __float_as_uint(VS(kk * 8 + qd + 4, dt * 8 + g));
                mma_tf32(o[dt], a0, a1, a2, a3, b0, b1);
            }
        }
    }

    // epilogue: normalize, tf32-round, write (B,N,E)
    const float inv0 = 1.f / l0, inv1 = 1.f / l1;
    float* ob = g_attn + ((size_t)b * NN + q0 + 16 * w) * EE + h * DD;
    #pragma unroll
    for (int dt = 0; dt < 8; dt++) {
        float2 v0 = make_float2(f2tf_f(o[dt][0] * inv0), f2tf_f(o[dt][1] * inv0));
        float2 v1 = make_float2(f2tf_f(o[dt][2] * inv1), f2tf_f(o[dt][3] * inv1));
        *(float2*)(ob + (size_t)g * EE + dt * 8 + 2 * qd) = v0;
        *(float2*)(ob + (size_t)(g + 8) * EE + dt * 8 + 2 * qd) = v1;
    }
}

// ---------------------------------------------------------------------------
// Stage C: out = g_attn @ Wf^T with tf32 mma. 128x128x32, cp.async pipelined.
// grid (8, 96), block 256, dynamic smem 73728 B.
// smem: As[2][128][36] | Ws[2][128][36]
// ---------------------------------------------------------------------------
#define GAS(bf, r, c_) sm[(bf) * 4608 + (r) * 36 + (c_)]
#define GWS(bf, r, c_) sm[9216 + (bf) * 4608 + (r) * 36 + (c_)]

__global__ __launch_bounds__(256, 2) void gemm_tf32_kernel(float* __restrict__ out)
{
    extern __shared__ float sm[];

    const int e0 = blockIdx.x * 128;
    const int m0 = blockIdx.y * 128;
    const int tid = threadIdx.x;
    const int w = tid >> 5;
    const int lane = tid & 31;
    const int g = lane >> 2, qd = lane & 3;
    const int mb = (w & 1) * 64;       // warp m offset
    const int nb = (w >> 1) * 32;      // warp n offset

    const float* Ab = g_attn + (size_t)m0 * EE;
    const float* Wb = g_wtf + (size_t)e0 * EE;

    const int rr = tid >> 3;           // 0..31
    const int c4 = (tid & 7) * 4;      // 0..28

    float acc[4][4][4] = {};

    // prologue: stage 0
    #pragma unroll
    for (int i = 0; i < 4; i++) {
        cp16(&GAS(0, rr + 32 * i, c4), Ab + (size_t)(rr + 32 * i) * EE + c4);
        cp16(&GWS(0, rr + 32 * i, c4), Wb + (size_t)(rr + 32 * i) * EE + c4);
    }
    cp_commit();

    int buf = 0;
    for (int kc = 0; kc < EE; kc += 32, buf ^= 1) {
        if (kc + 32 < EE) {
            #pragma unroll
            for (int i = 0; i < 4; i++) {
                cp16(&GAS(buf ^ 1, rr + 32 * i, c4), Ab + (size_t)(rr + 32 * i) * EE + kc + 32 + c4);
                cp16(&GWS(buf ^ 1, rr + 32 * i, c4), Wb + (size_t)(rr + 32 * i) * EE + kc + 32 + c4);
            }
            cp_commit();
            cp_wait1();
        } else {
            cp_wait0();
        }
        __syncthreads();

        #pragma unroll
        for (int kk = 0; kk < 4; kk++) {
            uint32_t a[4][4];
            #pragma unroll
            for (int mt = 0; mt < 4; mt++) {
                const int row = mb + mt * 16 + g;
                a[mt][0] = __float_as_uint(GAS(buf, row,     kk * 8 + qd));
                a[mt][1] = __float_as_uint(GAS(buf, row + 8, kk * 8 + qd));
                a[mt][2] = __float_as_uint(GAS(buf, row,     kk * 8 + qd + 4));
                a[mt][3] = __float_as_uint(GAS(buf, row + 8, kk * 8 + qd + 4));
            }
            #pragma unroll
            for (int nt = 0; nt < 4; nt++) {
                uint32_t b0 = __float_as_uint(GWS(buf, nb + nt * 8 + g, kk * 8 + qd));
                uint32_t b1 = __float_as_uint(GWS(buf, nb + nt * 8 + g, kk * 8 + qd + 4));
                #pragma unroll
                for (int mt = 0; mt < 4; mt++)
                    mma_tf32(acc[mt][nt], a[mt][0], a[mt][1], a[mt][2], a[mt][3], b0, b1);
            }
        }
        __syncthreads();
    }

    #pragma unroll
    for (int mt = 0; mt < 4; mt++) {
        const int row0 = m0 + mb + mt * 16 + g;
        #pragma unroll
        for (int nt = 0; nt < 4; nt++) {
            const int col = e0 + nb + nt * 8 + 2 * qd;
            *(float2*)(out + (size_t)row0 * EE + col) =
                make_float2(acc[mt][nt][0], acc[mt][nt][1]);
            *(float2*)(out + (size_t)(row0 + 8) * EE + col) =
                make_float2(acc[mt][nt][2], acc[mt][nt][3]);
        }
    }
}

// ---------------------------------------------------------------------------
extern "C" void kernel_launch(void* const* d_in, const int* in_sizes, int n_in,
                              void* d_out, int out_size)
{
    const float* q    = (const float*)d_in[0];
    const float* k    = (const float*)d_in[1];
    const float* v    = (const float*)d_in[2];
    const float* mask = (const float*)d_in[3];
    const float* Wq   = (const float*)d_in[4];
    const float* Wk   = (const float*)d_in[5];
    const float* Wv   = (const float*)d_in[6];
    const float* Wf   = (const float*)d_in[7];
    float* out = (float*)d_out;

    const int attn_smem = (128 * 76 + 64 * 76 + 64 * 72 + NN) * (int)sizeof(float); // 79872
    const int gemm_smem = (2 * 128 * 36 * 2) * (int)sizeof(float);                  // 73728
    cudaFuncSetAttribute(attn_tf32_kernel,
                         cudaFuncAttributeMaxDynamicSharedMemorySize, attn_smem);
    cudaFuncSetAttribute(gemm_tf32_kernel,
                         cudaFuncAttributeMaxDynamicSharedMemorySize, gemm_smem);

    proj_kernel<<<dim3(NN / 64, BB * HH, 3), 256>>>(q, k, v, Wq, Wk, Wv);
    cvtW_kernel<<<EE * EE / 1024, 256>>>(Wf);
    attn_tf32_kernel<<<dim3(NN / 128, BB * HH), 256, attn_smem>>>(mask);
    gemm_tf32_kernel<<<dim3(EE / 128, (BB * NN) / 128), 256, gemm_smem>>>(out);
}